// round 2
// baseline (speedup 1.0000x reference)
#include <cuda_runtime.h>

// VPNNetwork, 2 samples/thread + packed f32x2.
//   d_in[0] obs_flat [B,48] f32 | d_in[1] Phi_w [48,48] | d_in[2] Phi_b [48]
//   d_in[3] Logit_w [4,36]     | d_in[4] Logit_b [4]    | out [B,4] f32

#define BT  128
#define SPB 256              // samples per block
#define SS  259              // scratch stride (256 + pad; odd -> few STS conflicts)

typedef unsigned long long ull;

__device__ __forceinline__ ull pk(float a, float b) {
    ull d; asm("mov.b64 %0, {%1, %2};" : "=l"(d) : "f"(a), "f"(b)); return d;
}
__device__ __forceinline__ void upk(ull d, float& a, float& b) {
    asm("mov.b64 {%0, %1}, %2;" : "=f"(a), "=f"(b) : "l"(d));
}
__device__ __forceinline__ ull fma2(ull a, ull b, ull c) {
    ull d; asm("fma.rn.f32x2 %0, %1, %2, %3;" : "=l"(d) : "l"(a), "l"(b), "l"(c));
    return d;
}

// dynamic smem layout (floats):
//   scratch: 64*SS          [slot = cell*4+ch][sample], ch3 = V
//   sWt:     2304           sWt[i*48+o] = Pw[o*48+i]
//   sPb:     48
//   sLw:     144            sLw[k*4+a] = Lw[a*36+k]
//   sLb:     4
#define SCRATCH_F (64 * SS)
#define SWT_F     2304
#define SMEM_F    (SCRATCH_F + SWT_F + 48 + 144 + 4)
#define SMEM_BYTES ((SMEM_F * 4 + 15) & ~15)

__global__ __launch_bounds__(BT, 2) void vpn_kernel(
    const float* __restrict__ obs,
    const float* __restrict__ Pw,
    const float* __restrict__ Pb,
    const float* __restrict__ Lw,
    const float* __restrict__ Lb,
    float* __restrict__ out)
{
    extern __shared__ float smem[];
    float* scratch = smem;
    float* sWt = scratch + SCRATCH_F;
    float* sPb = sWt + SWT_F;
    float* sLw = sPb + 48;
    float* sLb = sLw + 144;

    const int tid = threadIdx.x;

    // ---- weights into shared (transposed) ----
    for (int idx = tid; idx < 48 * 48; idx += BT) {
        int o = idx / 48, i = idx - o * 48;
        sWt[i * 48 + o] = Pw[idx];
    }
    if (tid < 48) sPb[tid] = Pb[tid];
    for (int idx = tid; idx < 4 * 36; idx += BT) {
        int a = idx / 36, k = idx - a * 36;
        sLw[k * 4 + a] = Lw[idx];
    }
    if (tid < 4) sLb[tid] = Lb[tid];

    // ---- stage 256 samples of obs into element-major scratch ----
    const float4* g4 = reinterpret_cast<const float4*>(
        obs + (size_t)blockIdx.x * SPB * 48);
    #pragma unroll
    for (int k = 0; k < 24; k++) {
        int idx4 = tid + k * BT;            // 0..3071
        float4 q = g4[idx4];
        int s  = idx4 / 12;                 // sample 0..255
        int e0 = (idx4 - s * 12) * 4;
        float vv[4] = {q.x, q.y, q.z, q.w};
        #pragma unroll
        for (int j = 0; j < 4; j++) {
            int e = e0 + j;
            int cell = e / 3;
            int ch = e - cell * 3;
            scratch[(cell * 4 + ch) * SS + s] = vv[j];
        }
    }
    __syncthreads();

    // ---- Phi GEMV, two samples (tid, tid+128), output-pair packed ----
    ull a0[24], a1[24];
    const ull* pb2 = reinterpret_cast<const ull*>(sPb);
    #pragma unroll
    for (int k = 0; k < 24; k++) { ull b = pb2[k]; a0[k] = b; a1[k] = b; }

    int pos0 = 0, pos1 = 0;
    #pragma unroll 4
    for (int cellI = 0; cellI < 16; cellI++) {
        #pragma unroll
        for (int ch = 0; ch < 3; ch++) {
            int slot = (cellI * 4 + ch) * SS;
            float x0 = scratch[slot + tid];
            float x1 = scratch[slot + 128 + tid];
            if (ch == 1) {
                if (x0 != 0.0f) pos0 = cellI;
                if (x1 != 0.0f) pos1 = cellI;
            }
            ull xx0 = pk(x0, x0), xx1 = pk(x1, x1);
            const ulonglong2* wr = reinterpret_cast<const ulonglong2*>(
                sWt + (cellI * 3 + ch) * 48);
            #pragma unroll
            for (int j = 0; j < 12; j++) {
                ulonglong2 w = wr[j];
                a0[2 * j + 0] = fma2(xx0, w.x, a0[2 * j + 0]);
                a0[2 * j + 1] = fma2(xx0, w.y, a0[2 * j + 1]);
                a1[2 * j + 0] = fma2(xx1, w.x, a1[2 * j + 0]);
                a1[2 * j + 1] = fma2(xx1, w.y, a1[2 * j + 1]);
            }
        }
    }

    // unpack phi
    float ph0[48], ph1[48];
    #pragma unroll
    for (int k = 0; k < 24; k++) {
        upk(a0[k], ph0[2 * k], ph0[2 * k + 1]);
        upk(a1[k], ph1[2 * k], ph1[2 * k + 1]);
    }

    // ---- step-invariant VI constants, sample-pair packed ----
    // rr[dir][c] = (rin[nb]!=0) ? rin[nb]-rout[c] : 0 ; p[c] = phi[c*3+2]
    ull p_[16], v_[16];
    ull rrU[16], rrD[16], rrL[16], rrR[16];
    #pragma unroll
    for (int c = 0; c < 16; c++) {
        p_[c] = pk(ph0[c * 3 + 2], ph1[c * 3 + 2]);
        v_[c] = 0ULL;
        rrU[c] = rrD[c] = rrL[c] = rrR[c] = 0ULL;
    }
    #pragma unroll
    for (int h = 0; h < 4; h++) {
        #pragma unroll
        for (int w = 0; w < 4; w++) {
            int c = h * 4 + w;
            float ro0 = ph0[c * 3 + 1], ro1 = ph1[c * 3 + 1];
            if (h > 0) { float r0 = ph0[(c-4)*3], r1 = ph1[(c-4)*3];
                rrU[c] = pk(r0 != 0.f ? r0 - ro0 : 0.f, r1 != 0.f ? r1 - ro1 : 0.f); }
            if (h < 3) { float r0 = ph0[(c+4)*3], r1 = ph1[(c+4)*3];
                rrD[c] = pk(r0 != 0.f ? r0 - ro0 : 0.f, r1 != 0.f ? r1 - ro1 : 0.f); }
            if (w > 0) { float r0 = ph0[(c-1)*3], r1 = ph1[(c-1)*3];
                rrL[c] = pk(r0 != 0.f ? r0 - ro0 : 0.f, r1 != 0.f ? r1 - ro1 : 0.f); }
            if (w < 3) { float r0 = ph0[(c+1)*3], r1 = ph1[(c+1)*3];
                rrR[c] = pk(r0 != 0.f ? r0 - ro0 : 0.f, r1 != 0.f ? r1 - ro1 : 0.f); }
        }
    }

    // ---- value iteration: packed fma candidates, scalar max on halves ----
    #pragma unroll 4
    for (int k = 0; k < 20; k++) {
        ull nv[16];
        #pragma unroll
        for (int h = 0; h < 4; h++) {
            #pragma unroll
            for (int w = 0; w < 4; w++) {
                int c = h * 4 + w;
                float b0, b1; upk(v_[c], b0, b1);
                if (h > 0) { float c0, c1; upk(fma2(p_[c], v_[c-4], rrU[c]), c0, c1);
                             b0 = fmaxf(b0, c0); b1 = fmaxf(b1, c1); }
                if (h < 3) { float c0, c1; upk(fma2(p_[c], v_[c+4], rrD[c]), c0, c1);
                             b0 = fmaxf(b0, c0); b1 = fmaxf(b1, c1); }
                if (w > 0) { float c0, c1; upk(fma2(p_[c], v_[c-1], rrL[c]), c0, c1);
                             b0 = fmaxf(b0, c0); b1 = fmaxf(b1, c1); }
                if (w < 3) { float c0, c1; upk(fma2(p_[c], v_[c+1], rrR[c]), c0, c1);
                             b0 = fmaxf(b0, c0); b1 = fmaxf(b1, c1); }
                nv[c] = pk(b0, b1);
            }
        }
        #pragma unroll
        for (int c = 0; c < 16; c++) v_[c] = nv[c];
    }

    // ---- V into scratch ch3 (same-thread columns, no sync needed) ----
    #pragma unroll
    for (int c = 0; c < 16; c++) {
        float v0, v1; upk(v_[c], v0, v1);
        scratch[(c * 4 + 3) * SS + tid] = v0;
        scratch[(c * 4 + 3) * SS + 128 + tid] = v1;
    }

    // ---- gather + logit for both samples ----
    const ull* lb2 = reinterpret_cast<const ull*>(sLb);
    const ulonglong2* lw2 = reinterpret_cast<const ulonglong2*>(sLw);
    float4* out4 = reinterpret_cast<float4*>(out);

    #pragma unroll
    for (int s = 0; s < 2; s++) {
        int pos = s ? pos1 : pos0;
        int co = tid + s * 128;
        int ph_ = pos >> 2, pw_ = pos & 3;
        ull lgA = lb2[0], lgB = lb2[1];
        #pragma unroll
        for (int di = 0; di < 3; di++) {
            int h = ph_ - 1 + di;
            if ((unsigned)h < 4u) {
                #pragma unroll
                for (int dj = 0; dj < 3; dj++) {
                    int w = pw_ - 1 + dj;
                    if ((unsigned)w < 4u) {
                        int c = h * 4 + w;
                        int kb = (di * 3 + dj) * 4;
                        #pragma unroll
                        for (int ch = 0; ch < 4; ch++) {
                            float val = scratch[(c * 4 + ch) * SS + co];
                            ull vv = pk(val, val);
                            ulonglong2 lw = lw2[kb + ch];
                            lgA = fma2(vv, lw.x, lgA);
                            lgB = fma2(vv, lw.y, lgB);
                        }
                    }
                }
            }
        }
        float l0, l1, l2, l3;
        upk(lgA, l0, l1); upk(lgB, l2, l3);
        out4[blockIdx.x * SPB + s * 128 + tid] = make_float4(l0, l1, l2, l3);
    }
}

extern "C" void kernel_launch(void* const* d_in, const int* in_sizes, int n_in,
                              void* d_out, int out_size)
{
    const float* obs = (const float*)d_in[0];
    const float* Pw  = (const float*)d_in[1];
    const float* Pb  = (const float*)d_in[2];
    const float* Lw  = (const float*)d_in[3];
    const float* Lb  = (const float*)d_in[4];
    float* out = (float*)d_out;

    int B = in_sizes[0] / 48;                 // 262144
    int grid = B / SPB;                       // 1024
    cudaFuncSetAttribute(vpn_kernel,
                         cudaFuncAttributeMaxDynamicSharedMemorySize, SMEM_BYTES);
    vpn_kernel<<<grid, BT, SMEM_BYTES>>>(obs, Pw, Pb, Lw, Lb, out);
}

// round 3
// speedup vs baseline: 1.0554x; 1.0554x over previous
#include <cuda_runtime.h>

// VPNNetwork: block-tiled Phi GEMM (4 samples x 12 outputs per thread, one-hot
// ch1 exploited), phi handed off through shared, then per-sample VI + gather.
//
//   d_in[0] obs_flat [B,48] f32 | d_in[1] Phi_w [48,48] | d_in[2] Phi_b [48]
//   d_in[3] Logit_w [4,36]     | d_in[4] Logit_b [4]    | out [B,4] f32

#define BT   128            // threads per block
#define SPB  128            // samples per block
#define ST   132            // smem row stride (floats): 128 + pad, 16B-aligned

// shared layout (float offsets)
#define XS_OFF   0                      // obs element-major [e=3c+ch][s]  48*ST
#define PH_OFF   (XS_OFF + 48 * ST)     // phi element-major [o][s]        48*ST
#define VS_OFF   (PH_OFF + 48 * ST)     // V [c][s]                        16*ST
#define WT_OFF   (VS_OFF + 16 * ST)     // Wt[i*48+o] = Pw[o*48+i]         2304
#define PB_OFF   (WT_OFF + 2304)        // Phi_b                           48
#define LW_OFF   (PB_OFF + 48)          // sLw[k*4+a] = Lw[a*36+k]         144
#define LB_OFF   (LW_OFF + 144)         // Logit_b                         4
#define POS_OFF  (LB_OFF + 4)           // packed agent pos, 32 ints
#define SMEM_F   (POS_OFF + 32)
#define SMEM_BYTES (SMEM_F * 4)

__global__ __launch_bounds__(BT) void vpn_kernel(
    const float* __restrict__ obs,
    const float* __restrict__ Pw,
    const float* __restrict__ Pb,
    const float* __restrict__ Lw,
    const float* __restrict__ Lb,
    float* __restrict__ out)
{
    extern __shared__ float sm[];
    float* xs = sm + XS_OFF;
    float* ph = sm + PH_OFF;
    float* vs = sm + VS_OFF;
    float* wt = sm + WT_OFF;
    int*   spos = (int*)(sm + POS_OFF);

    const int tid = threadIdx.x;

    // ---- weights into shared ----
    for (int idx = tid; idx < 48 * 48; idx += BT) {
        int o = idx / 48, i = idx - o * 48;
        wt[i * 48 + o] = Pw[idx];               // wt[i][o]
    }
    if (tid < 48) sm[PB_OFF + tid] = Pb[tid];
    for (int idx = tid; idx < 4 * 36; idx += BT) {
        int a = idx / 36, k = idx - a * 36;
        sm[LW_OFF + k * 4 + a] = Lw[idx];
    }
    if (tid < 4) sm[LB_OFF + tid] = Lb[tid];

    // ---- stage 128 samples of obs, element-major xs[e][s] ----
    const float4* g4 = reinterpret_cast<const float4*>(
        obs + (size_t)blockIdx.x * SPB * 48);
    #pragma unroll
    for (int k = 0; k < 12; k++) {
        int idx4 = tid + k * BT;                // 0..1535
        float4 q = g4[idx4];
        int s  = idx4 / 12;
        int e0 = (idx4 - s * 12) * 4;
        xs[(e0 + 0) * ST + s] = q.x;
        xs[(e0 + 1) * ST + s] = q.y;
        xs[(e0 + 2) * ST + s] = q.z;
        xs[(e0 + 3) * ST + s] = q.w;
    }
    __syncthreads();

    // ================= Phase 1: Phi GEMM =================
    // thread tile: samples 4*mg..4*mg+3, outputs ng*12..ng*12+11
    const int mg = tid & 31;
    const int ng = tid >> 5;
    const int ob = ng * 12;

    float acc[4][12];
    {
        const float4* b4 = reinterpret_cast<const float4*>(sm + PB_OFF + ob);
        float4 b0 = b4[0], b1 = b4[1], b2 = b4[2];
        #pragma unroll
        for (int j = 0; j < 4; j++) {
            acc[j][0] = b0.x; acc[j][1] = b0.y; acc[j][2]  = b0.z; acc[j][3]  = b0.w;
            acc[j][4] = b1.x; acc[j][5] = b1.y; acc[j][6]  = b1.z; acc[j][7]  = b1.w;
            acc[j][8] = b2.x; acc[j][9] = b2.y; acc[j][10] = b2.z; acc[j][11] = b2.w;
        }
    }

    // dense inputs only: e = 3c+ch, ch in {0,2}
    #pragma unroll
    for (int c = 0; c < 16; c++) {
        #pragma unroll
        for (int chi = 0; chi < 2; chi++) {
            const int e = 3 * c + (chi ? 2 : 0);
            float4 xv = *reinterpret_cast<const float4*>(&xs[e * ST + 4 * mg]);
            const float4* wr = reinterpret_cast<const float4*>(&wt[e * 48 + ob]);
            float4 w0 = wr[0], w1 = wr[1], w2 = wr[2];
            float xa[4] = {xv.x, xv.y, xv.z, xv.w};
            #pragma unroll
            for (int j = 0; j < 4; j++) {
                float x = xa[j];
                acc[j][0]  = fmaf(x, w0.x, acc[j][0]);
                acc[j][1]  = fmaf(x, w0.y, acc[j][1]);
                acc[j][2]  = fmaf(x, w0.z, acc[j][2]);
                acc[j][3]  = fmaf(x, w0.w, acc[j][3]);
                acc[j][4]  = fmaf(x, w1.x, acc[j][4]);
                acc[j][5]  = fmaf(x, w1.y, acc[j][5]);
                acc[j][6]  = fmaf(x, w1.z, acc[j][6]);
                acc[j][7]  = fmaf(x, w1.w, acc[j][7]);
                acc[j][8]  = fmaf(x, w2.x, acc[j][8]);
                acc[j][9]  = fmaf(x, w2.y, acc[j][9]);
                acc[j][10] = fmaf(x, w2.z, acc[j][10]);
                acc[j][11] = fmaf(x, w2.w, acc[j][11]);
            }
        }
    }

    // one-hot ch1: find pos per sample, add W[:,3*pos+1] slice (x == 1.0)
    int pos[4] = {0, 0, 0, 0};
    #pragma unroll
    for (int c = 0; c < 16; c++) {
        float4 h = *reinterpret_cast<const float4*>(&xs[(3 * c + 1) * ST + 4 * mg]);
        if (h.x != 0.0f) pos[0] = c;
        if (h.y != 0.0f) pos[1] = c;
        if (h.z != 0.0f) pos[2] = c;
        if (h.w != 0.0f) pos[3] = c;
    }
    #pragma unroll
    for (int j = 0; j < 4; j++) {
        const float4* wr = reinterpret_cast<const float4*>(
            &wt[(3 * pos[j] + 1) * 48 + ob]);
        float4 w0 = wr[0], w1 = wr[1], w2 = wr[2];
        acc[j][0]  += w0.x; acc[j][1]  += w0.y; acc[j][2]  += w0.z; acc[j][3]  += w0.w;
        acc[j][4]  += w1.x; acc[j][5]  += w1.y; acc[j][6]  += w1.z; acc[j][7]  += w1.w;
        acc[j][8]  += w2.x; acc[j][9]  += w2.y; acc[j][10] += w2.z; acc[j][11] += w2.w;
    }
    if (ng == 0)
        spos[mg] = pos[0] | (pos[1] << 8) | (pos[2] << 16) | (pos[3] << 24);

    // store phi element-major: ph[o][4mg..4mg+3]
    #pragma unroll
    for (int o = 0; o < 12; o++) {
        *reinterpret_cast<float4*>(&ph[(ob + o) * ST + 4 * mg]) =
            make_float4(acc[0][o], acc[1][o], acc[2][o], acc[3][o]);
    }
    __syncthreads();

    // ================= Phase 2: VI + gather (1 sample = tid) =================
    float rin[16], rout[16], p_[16], v_[16];
    #pragma unroll
    for (int c = 0; c < 16; c++) {
        rin[c]  = ph[(3 * c + 0) * ST + tid];
        rout[c] = ph[(3 * c + 1) * ST + tid];
        p_[c]   = ph[(3 * c + 2) * ST + tid];
        v_[c]   = 0.0f;
    }

    // step-invariant rr[dir][c] = (rin[nb]!=0) ? rin[nb]-rout[c] : 0
    float rrU[16], rrD[16], rrL[16], rrR[16];
    #pragma unroll
    for (int h = 0; h < 4; h++) {
        #pragma unroll
        for (int w = 0; w < 4; w++) {
            int c = h * 4 + w;
            float ro = rout[c];
            if (h > 0) rrU[c] = (rin[c - 4] != 0.0f) ? rin[c - 4] - ro : 0.0f;
            if (h < 3) rrD[c] = (rin[c + 4] != 0.0f) ? rin[c + 4] - ro : 0.0f;
            if (w > 0) rrL[c] = (rin[c - 1] != 0.0f) ? rin[c - 1] - ro : 0.0f;
            if (w < 3) rrR[c] = (rin[c + 1] != 0.0f) ? rin[c + 1] - ro : 0.0f;
        }
    }

    #pragma unroll 4
    for (int k = 0; k < 20; k++) {
        float nv[16];
        #pragma unroll
        for (int h = 0; h < 4; h++) {
            #pragma unroll
            for (int w = 0; w < 4; w++) {
                int c = h * 4 + w;
                float best = v_[c];
                if (h > 0) best = fmaxf(best, fmaf(p_[c], v_[c - 4], rrU[c]));
                if (h < 3) best = fmaxf(best, fmaf(p_[c], v_[c + 4], rrD[c]));
                if (w > 0) best = fmaxf(best, fmaf(p_[c], v_[c - 1], rrL[c]));
                if (w < 3) best = fmaxf(best, fmaf(p_[c], v_[c + 1], rrR[c]));
                nv[c] = best;
            }
        }
        #pragma unroll
        for (int c = 0; c < 16; c++) v_[c] = nv[c];
    }

    // V into shared (own column, no sync needed before gather)
    #pragma unroll
    for (int c = 0; c < 16; c++) vs[c * ST + tid] = v_[c];

    int mypos = (spos[tid >> 2] >> ((tid & 3) * 8)) & 15;
    int phh = mypos >> 2, pww = mypos & 3;

    float lg0 = sm[LB_OFF + 0], lg1 = sm[LB_OFF + 1];
    float lg2 = sm[LB_OFF + 2], lg3 = sm[LB_OFF + 3];
    #pragma unroll
    for (int di = 0; di < 3; di++) {
        int h = phh - 1 + di;
        if ((unsigned)h < 4u) {
            #pragma unroll
            for (int dj = 0; dj < 3; dj++) {
                int w = pww - 1 + dj;
                if ((unsigned)w < 4u) {
                    int c = h * 4 + w;
                    int kb = (di * 3 + dj) * 4;
                    #pragma unroll
                    for (int ch = 0; ch < 4; ch++) {
                        float val = (ch < 3) ? xs[(c * 3 + ch) * ST + tid]
                                             : vs[c * ST + tid];
                        float4 lw = *reinterpret_cast<const float4*>(
                            sm + LW_OFF + (kb + ch) * 4);
                        lg0 = fmaf(val, lw.x, lg0);
                        lg1 = fmaf(val, lw.y, lg1);
                        lg2 = fmaf(val, lw.z, lg2);
                        lg3 = fmaf(val, lw.w, lg3);
                    }
                }
            }
        }
    }

    reinterpret_cast<float4*>(out)[blockIdx.x * SPB + tid] =
        make_float4(lg0, lg1, lg2, lg3);
}

extern "C" void kernel_launch(void* const* d_in, const int* in_sizes, int n_in,
                              void* d_out, int out_size)
{
    const float* obs = (const float*)d_in[0];
    const float* Pw  = (const float*)d_in[1];
    const float* Pb  = (const float*)d_in[2];
    const float* Lw  = (const float*)d_in[3];
    const float* Lb  = (const float*)d_in[4];
    float* out = (float*)d_out;

    int B = in_sizes[0] / 48;                 // 262144
    int grid = B / SPB;                       // 2048
    cudaFuncSetAttribute(vpn_kernel,
                         cudaFuncAttributeMaxDynamicSharedMemorySize, SMEM_BYTES);
    vpn_kernel<<<grid, BT, SMEM_BYTES>>>(obs, Pw, Pb, Lw, Lb, out);
}

// round 4
// speedup vs baseline: 1.0603x; 1.0047x over previous
#include <cuda_runtime.h>

// VPNNetwork: block-tiled Phi GEMM (4 samples x 12 outputs/thread, one-hot ch1
// exploited), phi overlaid on obs smem, register-resident VI, inverted gather.
//
//   d_in[0] obs_flat [B,48] f32 | d_in[1] Phi_w [48,48] | d_in[2] Phi_b [48]
//   d_in[3] Logit_w [4,36]     | d_in[4] Logit_b [4]    | out [B,4] f32

#define BT   128            // threads per block
#define SPB  128            // samples per block
#define ST   132            // smem row stride (floats), 16B-aligned rows

// shared layout (float offsets)
#define XP_OFF   0                      // phase1: obs [e][s]; phase2: phi [o][s]
#define WT_OFF   (XP_OFF + 48 * ST)     // Wt[i*48+o] = Pw[o*48+i]  (2304)
#define PB_OFF   (WT_OFF + 2304)        // Phi_b (48)
#define LW_OFF   (PB_OFF + 48)          // sLw[k*4+a] = Lw[a*36+k]  (144)
#define LB_OFF   (LW_OFF + 144)         // Logit_b (4)
#define POS_OFF  (LB_OFF + 4)           // packed agent pos, 32 ints
#define SMEM_F   (POS_OFF + 32)
#define SMEM_BYTES (SMEM_F * 4)

__global__ __launch_bounds__(BT, 5) void vpn_kernel(
    const float* __restrict__ obs,
    const float* __restrict__ Pw,
    const float* __restrict__ Pb,
    const float* __restrict__ Lw,
    const float* __restrict__ Lb,
    float* __restrict__ out)
{
    extern __shared__ float sm[];
    float* xp = sm + XP_OFF;            // obs in phase 1, phi in phase 2
    float* wt = sm + WT_OFF;
    int*   spos = (int*)(sm + POS_OFF);

    const int tid = threadIdx.x;

    // ---- weights into shared ----
    for (int idx = tid; idx < 48 * 48; idx += BT) {
        int o = idx / 48, i = idx - o * 48;
        wt[i * 48 + o] = Pw[idx];               // wt[i][o]
    }
    if (tid < 48) sm[PB_OFF + tid] = Pb[tid];
    for (int idx = tid; idx < 4 * 36; idx += BT) {
        int a = idx / 36, k = idx - a * 36;
        sm[LW_OFF + k * 4 + a] = Lw[idx];
    }
    if (tid < 4) sm[LB_OFF + tid] = Lb[tid];

    // ---- stage 128 samples of obs, element-major xp[e][s] ----
    const float4* g4 = reinterpret_cast<const float4*>(
        obs + (size_t)blockIdx.x * SPB * 48);
    #pragma unroll
    for (int k = 0; k < 12; k++) {
        int idx4 = tid + k * BT;                // 0..1535
        float4 q = g4[idx4];
        int s  = idx4 / 12;
        int e0 = (idx4 - s * 12) * 4;
        xp[(e0 + 0) * ST + s] = q.x;
        xp[(e0 + 1) * ST + s] = q.y;
        xp[(e0 + 2) * ST + s] = q.z;
        xp[(e0 + 3) * ST + s] = q.w;
    }
    __syncthreads();

    // ================= Phase 1: Phi GEMM =================
    // thread tile: samples 4*mg..4*mg+3, outputs ng*12..ng*12+11
    const int mg = tid & 31;
    const int ng = tid >> 5;
    const int ob = ng * 12;

    float acc[4][12];
    {
        const float4* b4 = reinterpret_cast<const float4*>(sm + PB_OFF + ob);
        float4 b0 = b4[0], b1 = b4[1], b2 = b4[2];
        #pragma unroll
        for (int j = 0; j < 4; j++) {
            acc[j][0] = b0.x; acc[j][1] = b0.y; acc[j][2]  = b0.z; acc[j][3]  = b0.w;
            acc[j][4] = b1.x; acc[j][5] = b1.y; acc[j][6]  = b1.z; acc[j][7]  = b1.w;
            acc[j][8] = b2.x; acc[j][9] = b2.y; acc[j][10] = b2.z; acc[j][11] = b2.w;
        }
    }

    // dense inputs only: e = 3c+ch, ch in {0,2}
    #pragma unroll
    for (int c = 0; c < 16; c++) {
        #pragma unroll
        for (int chi = 0; chi < 2; chi++) {
            const int e = 3 * c + (chi ? 2 : 0);
            float4 xv = *reinterpret_cast<const float4*>(&xp[e * ST + 4 * mg]);
            const float4* wr = reinterpret_cast<const float4*>(&wt[e * 48 + ob]);
            float4 w0 = wr[0], w1 = wr[1], w2 = wr[2];
            float xa[4] = {xv.x, xv.y, xv.z, xv.w};
            #pragma unroll
            for (int j = 0; j < 4; j++) {
                float x = xa[j];
                acc[j][0]  = fmaf(x, w0.x, acc[j][0]);
                acc[j][1]  = fmaf(x, w0.y, acc[j][1]);
                acc[j][2]  = fmaf(x, w0.z, acc[j][2]);
                acc[j][3]  = fmaf(x, w0.w, acc[j][3]);
                acc[j][4]  = fmaf(x, w1.x, acc[j][4]);
                acc[j][5]  = fmaf(x, w1.y, acc[j][5]);
                acc[j][6]  = fmaf(x, w1.z, acc[j][6]);
                acc[j][7]  = fmaf(x, w1.w, acc[j][7]);
                acc[j][8]  = fmaf(x, w2.x, acc[j][8]);
                acc[j][9]  = fmaf(x, w2.y, acc[j][9]);
                acc[j][10] = fmaf(x, w2.z, acc[j][10]);
                acc[j][11] = fmaf(x, w2.w, acc[j][11]);
            }
        }
    }

    // one-hot ch1: find pos per sample, add W[:,3*pos+1] slice (x == 1.0)
    int pos[4] = {0, 0, 0, 0};
    #pragma unroll
    for (int c = 0; c < 16; c++) {
        float4 h = *reinterpret_cast<const float4*>(&xp[(3 * c + 1) * ST + 4 * mg]);
        if (h.x != 0.0f) pos[0] = c;
        if (h.y != 0.0f) pos[1] = c;
        if (h.z != 0.0f) pos[2] = c;
        if (h.w != 0.0f) pos[3] = c;
    }
    #pragma unroll
    for (int j = 0; j < 4; j++) {
        const float4* wr = reinterpret_cast<const float4*>(
            &wt[(3 * pos[j] + 1) * 48 + ob]);
        float4 w0 = wr[0], w1 = wr[1], w2 = wr[2];
        acc[j][0]  += w0.x; acc[j][1]  += w0.y; acc[j][2]  += w0.z; acc[j][3]  += w0.w;
        acc[j][4]  += w1.x; acc[j][5]  += w1.y; acc[j][6]  += w1.z; acc[j][7]  += w1.w;
        acc[j][8]  += w2.x; acc[j][9]  += w2.y; acc[j][10] += w2.z; acc[j][11] += w2.w;
    }

    // all xp/wt reads done -> safe to overwrite xp with phi
    __syncthreads();

    if (ng == 0)
        spos[mg] = pos[0] | (pos[1] << 8) | (pos[2] << 16) | (pos[3] << 24);

    #pragma unroll
    for (int o = 0; o < 12; o++) {
        *reinterpret_cast<float4*>(&xp[(ob + o) * ST + 4 * mg]) =
            make_float4(acc[0][o], acc[1][o], acc[2][o], acc[3][o]);
    }
    __syncthreads();

    // ================= Phase 2: VI + gather (1 sample = tid) =================
    float rin[16], rout[16], p_[16], v_[16];
    #pragma unroll
    for (int c = 0; c < 16; c++) {
        rin[c]  = xp[(3 * c + 0) * ST + tid];
        rout[c] = xp[(3 * c + 1) * ST + tid];
        p_[c]   = xp[(3 * c + 2) * ST + tid];
        v_[c]   = 0.0f;
    }

    // step-invariant rr[dir][c] = (rin[nb]!=0) ? rin[nb]-rout[c] : 0
    float rrU[16], rrD[16], rrL[16], rrR[16];
    #pragma unroll
    for (int h = 0; h < 4; h++) {
        #pragma unroll
        for (int w = 0; w < 4; w++) {
            int c = h * 4 + w;
            float ro = rout[c];
            if (h > 0) rrU[c] = (rin[c - 4] != 0.0f) ? rin[c - 4] - ro : 0.0f;
            if (h < 3) rrD[c] = (rin[c + 4] != 0.0f) ? rin[c + 4] - ro : 0.0f;
            if (w > 0) rrL[c] = (rin[c - 1] != 0.0f) ? rin[c - 1] - ro : 0.0f;
            if (w < 3) rrR[c] = (rin[c + 1] != 0.0f) ? rin[c + 1] - ro : 0.0f;
        }
    }

    #pragma unroll 4
    for (int k = 0; k < 20; k++) {
        float nv[16];
        #pragma unroll
        for (int h = 0; h < 4; h++) {
            #pragma unroll
            for (int w = 0; w < 4; w++) {
                int c = h * 4 + w;
                float best = v_[c];
                if (h > 0) best = fmaxf(best, fmaf(p_[c], v_[c - 4], rrU[c]));
                if (h < 3) best = fmaxf(best, fmaf(p_[c], v_[c + 4], rrD[c]));
                if (w > 0) best = fmaxf(best, fmaf(p_[c], v_[c - 1], rrL[c]));
                if (w < 3) best = fmaxf(best, fmaf(p_[c], v_[c + 1], rrR[c]));
                nv[c] = best;
            }
        }
        #pragma unroll
        for (int c = 0; c < 16; c++) v_[c] = nv[c];
    }

    // ---- inverted gather: loop cells (compile-time), window index runtime ----
    int mypos = (spos[tid >> 2] >> ((tid & 3) * 8)) & 15;
    int phh = mypos >> 2, pww = mypos & 3;

    // ch1 contribution: agent cell is always window center (di=dj=1),
    // value exactly 1.0 -> add Lw column 17 ( (1*3+1)*4 + 1 ).
    float4 w17 = *reinterpret_cast<const float4*>(sm + LW_OFF + 17 * 4);
    float lg0 = sm[LB_OFF + 0] + w17.x;
    float lg1 = sm[LB_OFF + 1] + w17.y;
    float lg2 = sm[LB_OFF + 2] + w17.z;
    float lg3 = sm[LB_OFF + 3] + w17.w;

    const float* myobs = obs + ((size_t)blockIdx.x * SPB + tid) * 48;

    #pragma unroll
    for (int h = 0; h < 4; h++) {
        #pragma unroll
        for (int w = 0; w < 4; w++) {
            const int c = h * 4 + w;
            int di = h - phh + 1;               // window row of this cell
            int dj = w - pww + 1;
            if ((unsigned)di < 3u && (unsigned)dj < 3u) {
                int kb = (di * 3 + dj) * 4;
                float o0 = __ldg(myobs + 3 * c + 0);
                float o2 = __ldg(myobs + 3 * c + 2);
                float4 a0 = *reinterpret_cast<const float4*>(sm + LW_OFF + (kb + 0) * 4);
                float4 a2 = *reinterpret_cast<const float4*>(sm + LW_OFF + (kb + 2) * 4);
                float4 a3 = *reinterpret_cast<const float4*>(sm + LW_OFF + (kb + 3) * 4);
                float vv = v_[c];
                lg0 = fmaf(o0, a0.x, lg0); lg1 = fmaf(o0, a0.y, lg1);
                lg2 = fmaf(o0, a0.z, lg2); lg3 = fmaf(o0, a0.w, lg3);
                lg0 = fmaf(o2, a2.x, lg0); lg1 = fmaf(o2, a2.y, lg1);
                lg2 = fmaf(o2, a2.z, lg2); lg3 = fmaf(o2, a2.w, lg3);
                lg0 = fmaf(vv, a3.x, lg0); lg1 = fmaf(vv, a3.y, lg1);
                lg2 = fmaf(vv, a3.z, lg2); lg3 = fmaf(vv, a3.w, lg3);
            }
        }
    }

    reinterpret_cast<float4*>(out)[blockIdx.x * SPB + tid] =
        make_float4(lg0, lg1, lg2, lg3);
}

extern "C" void kernel_launch(void* const* d_in, const int* in_sizes, int n_in,
                              void* d_out, int out_size)
{
    const float* obs = (const float*)d_in[0];
    const float* Pw  = (const float*)d_in[1];
    const float* Pb  = (const float*)d_in[2];
    const float* Lw  = (const float*)d_in[3];
    const float* Lb  = (const float*)d_in[4];
    float* out = (float*)d_out;

    int B = in_sizes[0] / 48;                 // 262144
    int grid = B / SPB;                       // 2048
    cudaFuncSetAttribute(vpn_kernel,
                         cudaFuncAttributeMaxDynamicSharedMemorySize, SMEM_BYTES);
    vpn_kernel<<<grid, BT, SMEM_BYTES>>>(obs, Pw, Pb, Lw, Lb, out);
}

// round 5
// speedup vs baseline: 1.0612x; 1.0008x over previous
#include <cuda_runtime.h>

// VPNNetwork: block-tiled Phi GEMM (4 samples x 12 outputs/thread, one-hot ch1
// exploited), phi overlaid on obs smem, register-resident VI, inverted gather.
//
//   d_in[0] obs_flat [B,48] f32 | d_in[1] Phi_w [48,48] | d_in[2] Phi_b [48]
//   d_in[3] Logit_w [4,36]     | d_in[4] Logit_b [4]    | out [B,4] f32

#define BT   128            // threads per block
#define SPB  128            // samples per block
#define ST   132            // smem row stride (floats), 16B-aligned rows

// shared layout (float offsets)
#define XP_OFF   0                      // phase1: obs [e][s]; phase2: phi [o][s]
#define WT_OFF   (XP_OFF + 48 * ST)     // Wt[i*48+o] = Pw[o*48+i]  (2304)
#define PB_OFF   (WT_OFF + 2304)        // Phi_b (48)
#define LW_OFF   (PB_OFF + 48)          // sLw[k*4+a] = Lw[a*36+k]  (144)
#define LB_OFF   (LW_OFF + 144)         // Logit_b (4)
#define POS_OFF  (LB_OFF + 4)           // packed agent pos, 32 ints
#define SMEM_F   (POS_OFF + 32)
#define SMEM_BYTES (SMEM_F * 4)

__global__ __launch_bounds__(BT, 5) void vpn_kernel(
    const float* __restrict__ obs,
    const float* __restrict__ Pw,
    const float* __restrict__ Pb,
    const float* __restrict__ Lw,
    const float* __restrict__ Lb,
    float* __restrict__ out)
{
    extern __shared__ float sm[];
    float* xp = sm + XP_OFF;            // obs in phase 1, phi in phase 2
    float* wt = sm + WT_OFF;
    int*   spos = (int*)(sm + POS_OFF);

    const int tid = threadIdx.x;

    // ---- weights into shared ----
    for (int idx = tid; idx < 48 * 48; idx += BT) {
        int o = idx / 48, i = idx - o * 48;
        wt[i * 48 + o] = Pw[idx];               // wt[i][o]
    }
    if (tid < 48) sm[PB_OFF + tid] = Pb[tid];
    for (int idx = tid; idx < 4 * 36; idx += BT) {
        int a = idx / 36, k = idx - a * 36;
        sm[LW_OFF + k * 4 + a] = Lw[idx];
    }
    if (tid < 4) sm[LB_OFF + tid] = Lb[tid];

    // ---- stage 128 samples of obs, element-major xp[e][s] ----
    const float4* g4 = reinterpret_cast<const float4*>(
        obs + (size_t)blockIdx.x * SPB * 48);
    #pragma unroll
    for (int k = 0; k < 12; k++) {
        int idx4 = tid + k * BT;                // 0..1535
        float4 q = g4[idx4];
        int s  = idx4 / 12;
        int e0 = (idx4 - s * 12) * 4;
        xp[(e0 + 0) * ST + s] = q.x;
        xp[(e0 + 1) * ST + s] = q.y;
        xp[(e0 + 2) * ST + s] = q.z;
        xp[(e0 + 3) * ST + s] = q.w;
    }
    __syncthreads();

    // ================= Phase 1: Phi GEMM =================
    // thread tile: samples 4*mg..4*mg+3, outputs ng*12..ng*12+11
    const int mg = tid & 31;
    const int ng = tid >> 5;
    const int ob = ng * 12;

    float acc[4][12];
    {
        const float4* b4 = reinterpret_cast<const float4*>(sm + PB_OFF + ob);
        float4 b0 = b4[0], b1 = b4[1], b2 = b4[2];
        #pragma unroll
        for (int j = 0; j < 4; j++) {
            acc[j][0] = b0.x; acc[j][1] = b0.y; acc[j][2]  = b0.z; acc[j][3]  = b0.w;
            acc[j][4] = b1.x; acc[j][5] = b1.y; acc[j][6]  = b1.z; acc[j][7]  = b1.w;
            acc[j][8] = b2.x; acc[j][9] = b2.y; acc[j][10] = b2.z; acc[j][11] = b2.w;
        }
    }

    // dense inputs only: e = 3c+ch, ch in {0,2}
    #pragma unroll
    for (int c = 0; c < 16; c++) {
        #pragma unroll
        for (int chi = 0; chi < 2; chi++) {
            const int e = 3 * c + (chi ? 2 : 0);
            float4 xv = *reinterpret_cast<const float4*>(&xp[e * ST + 4 * mg]);
            const float4* wr = reinterpret_cast<const float4*>(&wt[e * 48 + ob]);
            float4 w0 = wr[0], w1 = wr[1], w2 = wr[2];
            float xa[4] = {xv.x, xv.y, xv.z, xv.w};
            #pragma unroll
            for (int j = 0; j < 4; j++) {
                float x = xa[j];
                acc[j][0]  = fmaf(x, w0.x, acc[j][0]);
                acc[j][1]  = fmaf(x, w0.y, acc[j][1]);
                acc[j][2]  = fmaf(x, w0.z, acc[j][2]);
                acc[j][3]  = fmaf(x, w0.w, acc[j][3]);
                acc[j][4]  = fmaf(x, w1.x, acc[j][4]);
                acc[j][5]  = fmaf(x, w1.y, acc[j][5]);
                acc[j][6]  = fmaf(x, w1.z, acc[j][6]);
                acc[j][7]  = fmaf(x, w1.w, acc[j][7]);
                acc[j][8]  = fmaf(x, w2.x, acc[j][8]);
                acc[j][9]  = fmaf(x, w2.y, acc[j][9]);
                acc[j][10] = fmaf(x, w2.z, acc[j][10]);
                acc[j][11] = fmaf(x, w2.w, acc[j][11]);
            }
        }
    }

    // one-hot ch1: find pos per sample, add W[:,3*pos+1] slice (x == 1.0)
    int pos[4] = {0, 0, 0, 0};
    #pragma unroll
    for (int c = 0; c < 16; c++) {
        float4 h = *reinterpret_cast<const float4*>(&xp[(3 * c + 1) * ST + 4 * mg]);
        if (h.x != 0.0f) pos[0] = c;
        if (h.y != 0.0f) pos[1] = c;
        if (h.z != 0.0f) pos[2] = c;
        if (h.w != 0.0f) pos[3] = c;
    }
    #pragma unroll
    for (int j = 0; j < 4; j++) {
        const float4* wr = reinterpret_cast<const float4*>(
            &wt[(3 * pos[j] + 1) * 48 + ob]);
        float4 w0 = wr[0], w1 = wr[1], w2 = wr[2];
        acc[j][0]  += w0.x; acc[j][1]  += w0.y; acc[j][2]  += w0.z; acc[j][3]  += w0.w;
        acc[j][4]  += w1.x; acc[j][5]  += w1.y; acc[j][6]  += w1.z; acc[j][7]  += w1.w;
        acc[j][8]  += w2.x; acc[j][9]  += w2.y; acc[j][10] += w2.z; acc[j][11] += w2.w;
    }

    // all xp/wt reads done -> safe to overwrite xp with phi
    __syncthreads();

    if (ng == 0)
        spos[mg] = pos[0] | (pos[1] << 8) | (pos[2] << 16) | (pos[3] << 24);

    #pragma unroll
    for (int o = 0; o < 12; o++) {
        *reinterpret_cast<float4*>(&xp[(ob + o) * ST + 4 * mg]) =
            make_float4(acc[0][o], acc[1][o], acc[2][o], acc[3][o]);
    }
    __syncthreads();

    // ================= Phase 2: VI + gather (1 sample = tid) =================
    float rin[16], rout[16], p_[16], v_[16];
    #pragma unroll
    for (int c = 0; c < 16; c++) {
        rin[c]  = xp[(3 * c + 0) * ST + tid];
        rout[c] = xp[(3 * c + 1) * ST + tid];
        p_[c]   = xp[(3 * c + 2) * ST + tid];
        v_[c]   = 0.0f;
    }

    // step-invariant rr[dir][c] = (rin[nb]!=0) ? rin[nb]-rout[c] : 0
    float rrU[16], rrD[16], rrL[16], rrR[16];
    #pragma unroll
    for (int h = 0; h < 4; h++) {
        #pragma unroll
        for (int w = 0; w < 4; w++) {
            int c = h * 4 + w;
            float ro = rout[c];
            if (h > 0) rrU[c] = (rin[c - 4] != 0.0f) ? rin[c - 4] - ro : 0.0f;
            if (h < 3) rrD[c] = (rin[c + 4] != 0.0f) ? rin[c + 4] - ro : 0.0f;
            if (w > 0) rrL[c] = (rin[c - 1] != 0.0f) ? rin[c - 1] - ro : 0.0f;
            if (w < 3) rrR[c] = (rin[c + 1] != 0.0f) ? rin[c + 1] - ro : 0.0f;
        }
    }

    #pragma unroll 4
    for (int k = 0; k < 20; k++) {
        float nv[16];
        #pragma unroll
        for (int h = 0; h < 4; h++) {
            #pragma unroll
            for (int w = 0; w < 4; w++) {
                int c = h * 4 + w;
                float best = v_[c];
                if (h > 0) best = fmaxf(best, fmaf(p_[c], v_[c - 4], rrU[c]));
                if (h < 3) best = fmaxf(best, fmaf(p_[c], v_[c + 4], rrD[c]));
                if (w > 0) best = fmaxf(best, fmaf(p_[c], v_[c - 1], rrL[c]));
                if (w < 3) best = fmaxf(best, fmaf(p_[c], v_[c + 1], rrR[c]));
                nv[c] = best;
            }
        }
        #pragma unroll
        for (int c = 0; c < 16; c++) v_[c] = nv[c];
    }

    // ---- inverted gather: loop cells (compile-time), window index runtime ----
    int mypos = (spos[tid >> 2] >> ((tid & 3) * 8)) & 15;
    int phh = mypos >> 2, pww = mypos & 3;

    // ch1 contribution: agent cell is always window center (di=dj=1),
    // value exactly 1.0 -> add Lw column 17 ( (1*3+1)*4 + 1 ).
    float4 w17 = *reinterpret_cast<const float4*>(sm + LW_OFF + 17 * 4);
    float lg0 = sm[LB_OFF + 0] + w17.x;
    float lg1 = sm[LB_OFF + 1] + w17.y;
    float lg2 = sm[LB_OFF + 2] + w17.z;
    float lg3 = sm[LB_OFF + 3] + w17.w;

    const float* myobs = obs + ((size_t)blockIdx.x * SPB + tid) * 48;

    #pragma unroll
    for (int h = 0; h < 4; h++) {
        #pragma unroll
        for (int w = 0; w < 4; w++) {
            const int c = h * 4 + w;
            int di = h - phh + 1;               // window row of this cell
            int dj = w - pww + 1;
            if ((unsigned)di < 3u && (unsigned)dj < 3u) {
                int kb = (di * 3 + dj) * 4;
                float o0 = __ldg(myobs + 3 * c + 0);
                float o2 = __ldg(myobs + 3 * c + 2);
                float4 a0 = *reinterpret_cast<const float4*>(sm + LW_OFF + (kb + 0) * 4);
                float4 a2 = *reinterpret_cast<const float4*>(sm + LW_OFF + (kb + 2) * 4);
                float4 a3 = *reinterpret_cast<const float4*>(sm + LW_OFF + (kb + 3) * 4);
                float vv = v_[c];
                lg0 = fmaf(o0, a0.x, lg0); lg1 = fmaf(o0, a0.y, lg1);
                lg2 = fmaf(o0, a0.z, lg2); lg3 = fmaf(o0, a0.w, lg3);
                lg0 = fmaf(o2, a2.x, lg0); lg1 = fmaf(o2, a2.y, lg1);
                lg2 = fmaf(o2, a2.z, lg2); lg3 = fmaf(o2, a2.w, lg3);
                lg0 = fmaf(vv, a3.x, lg0); lg1 = fmaf(vv, a3.y, lg1);
                lg2 = fmaf(vv, a3.z, lg2); lg3 = fmaf(vv, a3.w, lg3);
            }
        }
    }

    reinterpret_cast<float4*>(out)[blockIdx.x * SPB + tid] =
        make_float4(lg0, lg1, lg2, lg3);
}

extern "C" void kernel_launch(void* const* d_in, const int* in_sizes, int n_in,
                              void* d_out, int out_size)
{
    const float* obs = (const float*)d_in[0];
    const float* Pw  = (const float*)d_in[1];
    const float* Pb  = (const float*)d_in[2];
    const float* Lw  = (const float*)d_in[3];
    const float* Lb  = (const float*)d_in[4];
    float* out = (float*)d_out;

    int B = in_sizes[0] / 48;                 // 262144
    int grid = B / SPB;                       // 2048
    cudaFuncSetAttribute(vpn_kernel,
                         cudaFuncAttributeMaxDynamicSharedMemorySize, SMEM_BYTES);
    vpn_kernel<<<grid, BT, SMEM_BYTES>>>(obs, Pw, Pb, Lw, Lb, out);
}